// round 1
// baseline (speedup 1.0000x reference)
#include <cuda_runtime.h>
#include <math.h>

#define NN      50000
#define EE      320000
#define RR      3
#define IN_DIM  768
#define HID     256
#define OUT_DIM 64
#define KSTACK  (RR*HID)   // 768

// ---------------- scratch (device globals; no runtime allocation) ----------
__device__ float g_h  [(size_t)NN*HID];          // 51.2 MB
__device__ float g_h2 [(size_t)NN*HID];          // 51.2 MB
__device__ float g_agg[(size_t)NN*KSTACK];       // 153.6 MB
__device__ float g_aq [(size_t)NN*RR];
__device__ float g_ak [(size_t)NN*RR];
__device__ float g_alpha[EE];
__device__ float g_m  [NN];
__device__ float g_denom[NN];
__device__ float g_wq [RR*HID];
__device__ float g_wk [RR*HID];

// ---------------- SGEMM: C[M,N] = A[M,K] @ B[K,N] + bias (opt relu) --------
// BM=128 BN=128 BK=16, 256 threads, 8x8 per thread. K%16==0, N%128==0 assumed.
__global__ __launch_bounds__(256) void sgemm_bias(
    const float* __restrict__ A, const float* __restrict__ B,
    const float* __restrict__ bias, float* __restrict__ C,
    int M, int N, int K, int act)
{
    const int BM = 128, BN = 128, BK = 16;
    __shared__ float As[BK][BM];
    __shared__ float Bs[BK][BN];

    int tid = threadIdx.x;
    int m0 = blockIdx.y * BM, n0 = blockIdx.x * BN;
    int tx = tid & 15, ty = tid >> 4;

    float acc[8][8];
#pragma unroll
    for (int i = 0; i < 8; i++)
#pragma unroll
        for (int j = 0; j < 8; j++) acc[i][j] = 0.f;

    for (int k0 = 0; k0 < K; k0 += BK) {
        // load A tile (BMxBK) transposed into As
#pragma unroll
        for (int l = 0; l < 2; l++) {
            int f = tid + l * 256;            // 0..511 float4 slots
            int row = f >> 2, seg = f & 3;
            float4 v = make_float4(0.f, 0.f, 0.f, 0.f);
            int gr = m0 + row;
            if (gr < M) v = *(const float4*)&A[(size_t)gr * K + k0 + seg * 4];
            As[seg * 4 + 0][row] = v.x;
            As[seg * 4 + 1][row] = v.y;
            As[seg * 4 + 2][row] = v.z;
            As[seg * 4 + 3][row] = v.w;
        }
        // load B tile (BKxBN)
#pragma unroll
        for (int l = 0; l < 2; l++) {
            int f = tid + l * 256;
            int row = f >> 5, c4 = f & 31;
            *(float4*)&Bs[row][c4 * 4] =
                *(const float4*)&B[(size_t)(k0 + row) * N + n0 + c4 * 4];
        }
        __syncthreads();

#pragma unroll
        for (int k = 0; k < BK; k++) {
            float4 a0 = *(const float4*)&As[k][ty * 8];
            float4 a1 = *(const float4*)&As[k][ty * 8 + 4];
            float4 b0 = *(const float4*)&Bs[k][tx * 8];
            float4 b1 = *(const float4*)&Bs[k][tx * 8 + 4];
            float a[8] = {a0.x, a0.y, a0.z, a0.w, a1.x, a1.y, a1.z, a1.w};
            float b[8] = {b0.x, b0.y, b0.z, b0.w, b1.x, b1.y, b1.z, b1.w};
#pragma unroll
            for (int i = 0; i < 8; i++)
#pragma unroll
                for (int j = 0; j < 8; j++)
                    acc[i][j] = fmaf(a[i], b[j], acc[i][j]);
        }
        __syncthreads();
    }

#pragma unroll
    for (int i = 0; i < 8; i++) {
        int gr = m0 + ty * 8 + i;
        if (gr >= M) continue;
#pragma unroll
        for (int j4 = 0; j4 < 2; j4++) {
            int gc = n0 + tx * 8 + j4 * 4;
            float4 bv = *(const float4*)&bias[gc];
            float4 o;
            o.x = acc[i][j4 * 4 + 0] + bv.x;
            o.y = acc[i][j4 * 4 + 1] + bv.y;
            o.z = acc[i][j4 * 4 + 2] + bv.z;
            o.w = acc[i][j4 * 4 + 3] + bv.w;
            if (act) {
                o.x = fmaxf(o.x, 0.f); o.y = fmaxf(o.y, 0.f);
                o.z = fmaxf(o.z, 0.f); o.w = fmaxf(o.w, 0.f);
            }
            *(float4*)&C[(size_t)gr * N + gc] = o;
        }
    }
}

// wq[r] = W[r] @ q, wk[r] = W[r] @ k
__global__ void compute_wqk(const float* __restrict__ W, const float* __restrict__ q,
                            const float* __restrict__ k)
{
    int r = blockIdx.x;
    int i = threadIdx.x;   // 256
    const float* wr = &W[(size_t)r * HID * HID + (size_t)i * HID];
    float sq = 0.f, sk = 0.f;
#pragma unroll 8
    for (int j = 0; j < HID; j++) {
        float w = wr[j];
        sq = fmaf(w, q[j], sq);
        sk = fmaf(w, k[j], sk);
    }
    g_wq[r * HID + i] = sq;
    g_wk[r * HID + i] = sk;
}

// aq[n,r] = h[n]·wq[r], ak[n,r] = h[n]·wk[r] ; one warp per node
__global__ void node_dots(const float* __restrict__ h)
{
    int warp = (blockIdx.x * blockDim.x + threadIdx.x) >> 5;
    int lane = threadIdx.x & 31;
    if (warp >= NN) return;
    float sq[RR] = {0.f, 0.f, 0.f}, sk[RR] = {0.f, 0.f, 0.f};
#pragma unroll
    for (int i = 0; i < 8; i++) {
        int idx = i * 32 + lane;
        float hv = h[(size_t)warp * HID + idx];
#pragma unroll
        for (int r = 0; r < RR; r++) {
            sq[r] = fmaf(hv, g_wq[r * HID + idx], sq[r]);
            sk[r] = fmaf(hv, g_wk[r * HID + idx], sk[r]);
        }
    }
#pragma unroll
    for (int off = 16; off; off >>= 1) {
#pragma unroll
        for (int r = 0; r < RR; r++) {
            sq[r] += __shfl_xor_sync(0xFFFFFFFFu, sq[r], off);
            sk[r] += __shfl_xor_sync(0xFFFFFFFFu, sk[r], off);
        }
    }
    if (lane == 0) {
#pragma unroll
        for (int r = 0; r < RR; r++) {
            g_aq[(size_t)warp * RR + r] = sq[r];
            g_ak[(size_t)warp * RR + r] = sk[r];
        }
    }
}

__global__ void init_md()
{
    int n = blockIdx.x * blockDim.x + threadIdx.x;
    if (n < NN) { g_m[n] = -INFINITY; g_denom[n] = 0.f; }
}

__global__ void zero_agg()
{
    size_t i = (size_t)blockIdx.x * blockDim.x + threadIdx.x;
    if (i < (size_t)NN * KSTACK / 4)
        ((float4*)g_agg)[i] = make_float4(0.f, 0.f, 0.f, 0.f);
}

// pass1: alpha = leaky_relu(aq[dst,et] + ak[src,et]); segment max into m[dst]
__global__ void edge_pass1(const int* __restrict__ ei, const int* __restrict__ et)
{
    int e = blockIdx.x * blockDim.x + threadIdx.x;
    if (e >= EE) return;
    int s = ei[e], d = ei[EE + e], r = et[e];
    float a = g_aq[(size_t)d * RR + r] + g_ak[(size_t)s * RR + r];
    a = a > 0.f ? a : 0.2f * a;
    g_alpha[e] = a;
    if (a >= 0.f) atomicMax((int*)&g_m[d], __float_as_int(a));
    else          atomicMin((unsigned int*)&g_m[d], __float_as_uint(a));
}

// pass2: ea = exp(alpha - m[dst]); denom[dst] += ea
__global__ void edge_pass2(const int* __restrict__ ei)
{
    int e = blockIdx.x * blockDim.x + threadIdx.x;
    if (e >= EE) return;
    int d = ei[EE + e];
    float ea = expf(g_alpha[e] - g_m[d]);
    g_alpha[e] = ea;
    atomicAdd(&g_denom[d], ea);
}

// pass3: agg[dst, et*256 + c] += (ea/denom) * h[src, c] ; one warp per edge
__global__ void edge_pass3(const int* __restrict__ ei, const int* __restrict__ et,
                           const float* __restrict__ h)
{
    int e = (int)((blockIdx.x * blockDim.x + threadIdx.x) >> 5);
    int lane = threadIdx.x & 31;
    if (e >= EE) return;
    int s = ei[e], d = ei[EE + e], r = et[e];
    float coef = g_alpha[e] / (g_denom[d] + 1e-16f);
    const float4* hs = (const float4*)&h[(size_t)s * HID];
    float* ag = &g_agg[(size_t)d * KSTACK + r * HID];
    float4 v0 = hs[lane];
    float4 v1 = hs[32 + lane];
    int c0 = lane * 4;
    atomicAdd(&ag[c0 + 0], coef * v0.x);
    atomicAdd(&ag[c0 + 1], coef * v0.y);
    atomicAdd(&ag[c0 + 2], coef * v0.z);
    atomicAdd(&ag[c0 + 3], coef * v0.w);
    atomicAdd(&ag[128 + c0 + 0], coef * v1.x);
    atomicAdd(&ag[128 + c0 + 1], coef * v1.y);
    atomicAdd(&ag[128 + c0 + 2], coef * v1.z);
    atomicAdd(&ag[128 + c0 + 3], coef * v1.w);
}

// head: y = relu(h @ w_out + b_out) @ w_cls + b_cls ; one block (64 thr) per node
__global__ __launch_bounds__(64) void head_kernel(
    const float* __restrict__ h, const float* __restrict__ w_out,
    const float* __restrict__ b_out, const float* __restrict__ w_cls,
    const float* __restrict__ b_cls, float* __restrict__ y)
{
    int n = blockIdx.x;
    int o = threadIdx.x;  // 0..63
    __shared__ float hs[HID];
    __shared__ float ts[OUT_DIM];
#pragma unroll
    for (int i = o; i < HID; i += 64) hs[i] = h[(size_t)n * HID + i];
    __syncthreads();
    float s = b_out[o];
#pragma unroll 8
    for (int c = 0; c < HID; c++)
        s = fmaf(hs[c], w_out[c * OUT_DIM + o], s);
    ts[o] = fmaxf(s, 0.f);
    __syncthreads();
    if (o < 2) {
        float acc = b_cls[o];
#pragma unroll
        for (int j = 0; j < OUT_DIM; j++)
            acc = fmaf(ts[j], w_cls[j * 2 + o], acc);
        y[(size_t)n * 2 + o] = acc;
    }
}

// ---------------------------------------------------------------------------
static void run_conv(const float* hin, float* hout,
                     const float* W, const float* q, const float* k,
                     const float* b, const int* ei, const int* et, float* agg)
{
    compute_wqk<<<RR, 256>>>(W, q, k);
    node_dots<<<(NN + 7) / 8, 256>>>(hin);
    init_md<<<(NN + 255) / 256, 256>>>();
    zero_agg<<<(int)(((size_t)NN * KSTACK / 4 + 255) / 256), 256>>>();
    edge_pass1<<<(EE + 255) / 256, 256>>>(ei, et);
    edge_pass2<<<(EE + 255) / 256, 256>>>(ei);
    edge_pass3<<<(EE * 32 + 255) / 256, 256>>>(ei, et, hin);
    // out = agg @ W_stacked + b   (W is [R,HID,HID] contiguous == [768,256])
    dim3 grid(HID / 128, (NN + 127) / 128);
    sgemm_bias<<<grid, 256>>>(agg, W, b, hout, NN, HID, KSTACK, 0);
}

extern "C" void kernel_launch(void* const* d_in, const int* in_sizes, int n_in,
                              void* d_out, int out_size)
{
    const float* x       = (const float*)d_in[0];
    const int*   ei      = (const int*)  d_in[1];   // [2,E]
    const int*   et      = (const int*)  d_in[2];   // [E]
    const float* w_in    = (const float*)d_in[3];
    const float* b_in    = (const float*)d_in[4];
    const float* c1_w    = (const float*)d_in[5];
    const float* c1_q    = (const float*)d_in[6];
    const float* c1_k    = (const float*)d_in[7];
    const float* c1_b    = (const float*)d_in[8];
    const float* c2_w    = (const float*)d_in[9];
    const float* c2_q    = (const float*)d_in[10];
    const float* c2_k    = (const float*)d_in[11];
    const float* c2_b    = (const float*)d_in[12];
    const float* w_out   = (const float*)d_in[13];
    const float* b_out   = (const float*)d_in[14];
    const float* w_cls   = (const float*)d_in[15];
    const float* b_cls   = (const float*)d_in[16];
    float* y = (float*)d_out;

    float *h, *h2, *agg;
    cudaGetSymbolAddress((void**)&h,   g_h);
    cudaGetSymbolAddress((void**)&h2,  g_h2);
    cudaGetSymbolAddress((void**)&agg, g_agg);

    // 1) h = relu(x @ w_in + b_in)
    {
        dim3 grid(HID / 128, (NN + 127) / 128);
        sgemm_bias<<<grid, 256>>>(x, w_in, b_in, h, NN, HID, IN_DIM, 1);
    }
    // 2) conv1: h -> h2
    run_conv(h, h2, c1_w, c1_q, c1_k, c1_b, ei, et, agg);
    // 3) conv2: h2 -> h
    run_conv(h2, h, c2_w, c2_q, c2_k, c2_b, ei, et, agg);
    // 4) head
    head_kernel<<<NN, 64>>>(h, w_out, b_out, w_cls, b_cls, y);
}

// round 4
// speedup vs baseline: 1.3676x; 1.3676x over previous
#include <cuda_runtime.h>
#include <cuda_bf16.h>
#include <math.h>
#include <cstdint>

#define NN      50000
#define EE      320000
#define RR      3
#define IN_DIM  768
#define HID     256
#define OUT_DIM 64
#define KSTACK  (RR*HID)   // 768 == IN_DIM: all 3 big GEMMs share K=768, N=256

// ---------------- scratch (device globals; no runtime allocation) ----------
__device__ float g_h  [(size_t)NN*HID];
__device__ float g_h2 [(size_t)NN*HID];
__device__ float g_agg[(size_t)NN*KSTACK];
__device__ float g_aq [(size_t)NN*RR];
__device__ float g_ak [(size_t)NN*RR];
__device__ float g_alpha[EE];
__device__ float g_m  [NN];
__device__ float g_denom[NN];
__device__ float g_wq [RR*HID];
__device__ float g_wk [RR*HID];
__device__ __nv_bfloat16 g_bthi[(size_t)HID*KSTACK];  // B^T hi [256,768]
__device__ __nv_bfloat16 g_btlo[(size_t)HID*KSTACK];  // B^T lo [256,768]

// ======================= HMMA GEMM (split-bf16 x3) =========================
// C[M,256] = A[M,768] @ B[768,256] + bias (opt relu)
// mma.sync.aligned.m16n8k16.row.col.f32.bf16.bf16.f32
// CTA tile 128x128 (grid.x = N/128 = 2), 8 warps as 2(M)x4(N) -> warp 64x32.
// smem: A[m][k] and B^T[n][k] bf16, row stride 40 (pad 8) for bank spread.

#define SROW 40   // bf16 elements per smem row (32 + 8 pad)

__device__ __forceinline__ void mma_bf16(float* c, const uint32_t* a, const uint32_t* b) {
    asm volatile(
        "mma.sync.aligned.m16n8k16.row.col.f32.bf16.bf16.f32 "
        "{%0,%1,%2,%3}, {%4,%5,%6,%7}, {%8,%9}, {%0,%1,%2,%3};"
        : "+f"(c[0]), "+f"(c[1]), "+f"(c[2]), "+f"(c[3])
        : "r"(a[0]), "r"(a[1]), "r"(a[2]), "r"(a[3]), "r"(b[0]), "r"(b[1]));
}

__global__ __launch_bounds__(256, 1) void gemm_hmma(
    const float* __restrict__ A, const __nv_bfloat16* __restrict__ Bthi,
    const __nv_bfloat16* __restrict__ Btlo, const float* __restrict__ bias,
    float* __restrict__ C, int M, int act)
{
    __shared__ __align__(16) __nv_bfloat16 sAhi[128 * SROW];
    __shared__ __align__(16) __nv_bfloat16 sAlo[128 * SROW];
    __shared__ __align__(16) __nv_bfloat16 sBhi[128 * SROW];
    __shared__ __align__(16) __nv_bfloat16 sBlo[128 * SROW];

    const int tid = threadIdx.x, wid = tid >> 5, lane = tid & 31;
    const int g = lane >> 2, t = lane & 3;
    const int m0 = blockIdx.y * 128, n0 = blockIdx.x * 128;
    const int warp_m = wid >> 2, warp_n = wid & 3;   // 2 x 4

    float acc[4][4][4];
#pragma unroll
    for (int i = 0; i < 4; i++)
#pragma unroll
        for (int j = 0; j < 4; j++)
#pragma unroll
            for (int k = 0; k < 4; k++) acc[i][j][k] = 0.f;

    // staging: thread covers row (tid>>1), k-half (tid&1)*16
    const int srow = tid >> 1, shalf = (tid & 1) * 16;
    const bool arow_ok = (m0 + srow) < M;
    const float* agp = A + (size_t)(m0 + srow) * 768 + shalf;
    const __nv_bfloat16* bhp = Bthi + (size_t)(n0 + srow) * 768 + shalf;
    const __nv_bfloat16* blp = Btlo + (size_t)(n0 + srow) * 768 + shalf;

    float4 a_st[4];
    uint4  bh_st[2], bl_st[2];

    auto load_stage = [&](int kb) {
        if (arow_ok) {
            const float4* ap = (const float4*)(agp + kb);
#pragma unroll
            for (int i = 0; i < 4; i++) a_st[i] = ap[i];
        } else {
#pragma unroll
            for (int i = 0; i < 4; i++) a_st[i] = make_float4(0.f, 0.f, 0.f, 0.f);
        }
        const uint4* bh = (const uint4*)(bhp + kb);
        const uint4* bl = (const uint4*)(blp + kb);
        bh_st[0] = bh[0]; bh_st[1] = bh[1];
        bl_st[0] = bl[0]; bl_st[1] = bl[1];
    };

    auto commit_stage = [&]() {
        // A: 16 fp32 -> 16 bf16 hi + 16 bf16 lo
        uint32_t hi[8], lo[8];
        const float* f = (const float*)a_st;
#pragma unroll
        for (int i = 0; i < 8; i++) {
            float v0 = f[2 * i], v1 = f[2 * i + 1];
            __nv_bfloat16 h0 = __float2bfloat16_rn(v0);
            __nv_bfloat16 h1 = __float2bfloat16_rn(v1);
            __nv_bfloat16 l0 = __float2bfloat16_rn(v0 - __bfloat162float(h0));
            __nv_bfloat16 l1 = __float2bfloat16_rn(v1 - __bfloat162float(h1));
            hi[i] = (uint32_t)__bfloat16_as_ushort(h0) | ((uint32_t)__bfloat16_as_ushort(h1) << 16);
            lo[i] = (uint32_t)__bfloat16_as_ushort(l0) | ((uint32_t)__bfloat16_as_ushort(l1) << 16);
        }
        int off = srow * SROW + shalf;
        *(uint4*)(sAhi + off)     = make_uint4(hi[0], hi[1], hi[2], hi[3]);
        *(uint4*)(sAhi + off + 8) = make_uint4(hi[4], hi[5], hi[6], hi[7]);
        *(uint4*)(sAlo + off)     = make_uint4(lo[0], lo[1], lo[2], lo[3]);
        *(uint4*)(sAlo + off + 8) = make_uint4(lo[4], lo[5], lo[6], lo[7]);
        *(uint4*)(sBhi + off)     = bh_st[0];
        *(uint4*)(sBhi + off + 8) = bh_st[1];
        *(uint4*)(sBlo + off)     = bl_st[0];
        *(uint4*)(sBlo + off + 8) = bl_st[1];
    };

    load_stage(0);

    for (int it = 0; it < 24; it++) {
        __syncthreads();               // smem free (prev MMAs done)
        commit_stage();
        __syncthreads();
        if (it + 1 < 24) load_stage((it + 1) * 32);   // prefetch overlaps MMA

#pragma unroll
        for (int ks = 0; ks < 2; ks++) {
            const int kk = ks * 16 + 2 * t;
            uint32_t ahi[4][4], alo[4][4], bhi[4][2], blo[4][2];
#pragma unroll
            for (int mt = 0; mt < 4; mt++) {
                int r0 = (warp_m * 64 + mt * 16 + g) * SROW;
                int r1 = r0 + 8 * SROW;
                ahi[mt][0] = *(const uint32_t*)(sAhi + r0 + kk);
                ahi[mt][1] = *(const uint32_t*)(sAhi + r1 + kk);
                ahi[mt][2] = *(const uint32_t*)(sAhi + r0 + kk + 8);
                ahi[mt][3] = *(const uint32_t*)(sAhi + r1 + kk + 8);
                alo[mt][0] = *(const uint32_t*)(sAlo + r0 + kk);
                alo[mt][1] = *(const uint32_t*)(sAlo + r1 + kk);
                alo[mt][2] = *(const uint32_t*)(sAlo + r0 + kk + 8);
                alo[mt][3] = *(const uint32_t*)(sAlo + r1 + kk + 8);
            }
#pragma unroll
            for (int nt = 0; nt < 4; nt++) {
                int rb = (warp_n * 32 + nt * 8 + g) * SROW;
                bhi[nt][0] = *(const uint32_t*)(sBhi + rb + kk);
                bhi[nt][1] = *(const uint32_t*)(sBhi + rb + kk + 8);
                blo[nt][0] = *(const uint32_t*)(sBlo + rb + kk);
                blo[nt][1] = *(const uint32_t*)(sBlo + rb + kk + 8);
            }
#pragma unroll
            for (int mt = 0; mt < 4; mt++)
#pragma unroll
                for (int nt = 0; nt < 4; nt++) {
                    mma_bf16(acc[mt][nt], ahi[mt], bhi[nt]);
                    mma_bf16(acc[mt][nt], ahi[mt], blo[nt]);
                    mma_bf16(acc[mt][nt], alo[mt], bhi[nt]);
                }
        }
    }

    // epilogue
#pragma unroll
    for (int mt = 0; mt < 4; mt++) {
#pragma unroll
        for (int nt = 0; nt < 4; nt++) {
            int col = n0 + warp_n * 32 + nt * 8 + 2 * t;
            float b0 = __ldg(&bias[col]), b1 = __ldg(&bias[col + 1]);
            int row0 = m0 + warp_m * 64 + mt * 16 + g;
            int row1 = row0 + 8;
            float2 o0 = make_float2(acc[mt][nt][0] + b0, acc[mt][nt][1] + b1);
            float2 o1 = make_float2(acc[mt][nt][2] + b0, acc[mt][nt][3] + b1);
            if (act) {
                o0.x = fmaxf(o0.x, 0.f); o0.y = fmaxf(o0.y, 0.f);
                o1.x = fmaxf(o1.x, 0.f); o1.y = fmaxf(o1.y, 0.f);
            }
            if (row0 < M) *(float2*)&C[(size_t)row0 * 256 + col] = o0;
            if (row1 < M) *(float2*)&C[(size_t)row1 * 256 + col] = o1;
        }
    }
}

// B conversion: W[768,256] fp32 -> Bt hi/lo [256,768] bf16 (transposed+split)
__global__ void convert_B(const float* __restrict__ W)
{
    int idx = blockIdx.x * 256 + threadIdx.x;   // 768*256
    int k = idx >> 8, n = idx & 255;
    float v = W[idx];
    __nv_bfloat16 hi = __float2bfloat16_rn(v);
    __nv_bfloat16 lo = __float2bfloat16_rn(v - __bfloat162float(hi));
    g_bthi[(size_t)n * 768 + k] = hi;
    g_btlo[(size_t)n * 768 + k] = lo;
}

// ====================== attention / edge kernels ===========================
__global__ void compute_wqk(const float* __restrict__ W, const float* __restrict__ q,
                            const float* __restrict__ k)
{
    int r = blockIdx.x, i = threadIdx.x;
    const float* wr = &W[(size_t)r * HID * HID + (size_t)i * HID];
    float sq = 0.f, sk = 0.f;
#pragma unroll 8
    for (int j = 0; j < HID; j++) {
        float w = wr[j];
        sq = fmaf(w, q[j], sq);
        sk = fmaf(w, k[j], sk);
    }
    g_wq[r * HID + i] = sq;
    g_wk[r * HID + i] = sk;
}

__global__ void node_dots(const float* __restrict__ h)
{
    int warp = (blockIdx.x * blockDim.x + threadIdx.x) >> 5;
    int lane = threadIdx.x & 31;
    if (warp >= NN) return;
    float sq[RR] = {0.f, 0.f, 0.f}, sk[RR] = {0.f, 0.f, 0.f};
#pragma unroll
    for (int i = 0; i < 8; i++) {
        int idx = i * 32 + lane;
        float hv = h[(size_t)warp * HID + idx];
#pragma unroll
        for (int r = 0; r < RR; r++) {
            sq[r] = fmaf(hv, g_wq[r * HID + idx], sq[r]);
            sk[r] = fmaf(hv, g_wk[r * HID + idx], sk[r]);
        }
    }
#pragma unroll
    for (int off = 16; off; off >>= 1) {
#pragma unroll
        for (int r = 0; r < RR; r++) {
            sq[r] += __shfl_xor_sync(0xFFFFFFFFu, sq[r], off);
            sk[r] += __shfl_xor_sync(0xFFFFFFFFu, sk[r], off);
        }
    }
    if (lane == 0) {
#pragma unroll
        for (int r = 0; r < RR; r++) {
            g_aq[(size_t)warp * RR + r] = sq[r];
            g_ak[(size_t)warp * RR + r] = sk[r];
        }
    }
}

__global__ void init_md()
{
    int n = blockIdx.x * blockDim.x + threadIdx.x;
    if (n < NN) { g_m[n] = -INFINITY; g_denom[n] = 0.f; }
}

__global__ void edge_pass1(const int* __restrict__ ei, const int* __restrict__ et)
{
    int e = blockIdx.x * blockDim.x + threadIdx.x;
    if (e >= EE) return;
    int s = ei[e], d = ei[EE + e], r = et[e];
    float a = g_aq[(size_t)d * RR + r] + g_ak[(size_t)s * RR + r];
    a = a > 0.f ? a : 0.2f * a;
    g_alpha[e] = a;
    if (a >= 0.f) atomicMax((int*)&g_m[d], __float_as_int(a));
    else          atomicMin((unsigned int*)&g_m[d], __float_as_uint(a));
}

__global__ void edge_pass2(const int* __restrict__ ei)
{
    int e = blockIdx.x * blockDim.x + threadIdx.x;
    if (e >= EE) return;
    int d = ei[EE + e];
    float ea = expf(g_alpha[e] - g_m[d]);
    g_alpha[e] = ea;
    atomicAdd(&g_denom[d], ea);
}

__global__ void edge_pass3(const int* __restrict__ ei, const int* __restrict__ et,
                           const float* __restrict__ h)
{
    int e = (int)((blockIdx.x * blockDim.x + threadIdx.x) >> 5);
    int lane = threadIdx.x & 31;
    if (e >= EE) return;
    int s = ei[e], d = ei[EE + e], r = et[e];
    float coef = g_alpha[e] / (g_denom[d] + 1e-16f);
    const float4* hs = (const float4*)&h[(size_t)s * HID];
    float* ag = &g_agg[(size_t)d * KSTACK + r * HID];
    float4 v0 = hs[lane];
    float4 v1 = hs[32 + lane];
    int c0 = lane * 4;
    atomicAdd(&ag[c0 + 0], coef * v0.x);
    atomicAdd(&ag[c0 + 1], coef * v0.y);
    atomicAdd(&ag[c0 + 2], coef * v0.z);
    atomicAdd(&ag[c0 + 3], coef * v0.w);
    atomicAdd(&ag[128 + c0 + 0], coef * v1.x);
    atomicAdd(&ag[128 + c0 + 1], coef * v1.y);
    atomicAdd(&ag[128 + c0 + 2], coef * v1.z);
    atomicAdd(&ag[128 + c0 + 3], coef * v1.w);
}

__global__ __launch_bounds__(64) void head_kernel(
    const float* __restrict__ h, const float* __restrict__ w_out,
    const float* __restrict__ b_out, const float* __restrict__ w_cls,
    const float* __restrict__ b_cls, float* __restrict__ y)
{
    int n = blockIdx.x;
    int o = threadIdx.x;
    __shared__ float hs[HID];
    __shared__ float ts[OUT_DIM];
#pragma unroll
    for (int i = o; i < HID; i += 64) hs[i] = h[(size_t)n * HID + i];
    __syncthreads();
    float s = b_out[o];
#pragma unroll 8
    for (int c = 0; c < HID; c++)
        s = fmaf(hs[c], w_out[c * OUT_DIM + o], s);
    ts[o] = fmaxf(s, 0.f);
    __syncthreads();
    if (o < 2) {
        float acc = b_cls[o];
#pragma unroll
        for (int j = 0; j < OUT_DIM; j++)
            acc = fmaf(ts[j], w_cls[j * 2 + o], acc);
        y[(size_t)n * 2 + o] = acc;
    }
}

// ---------------------------------------------------------------------------
static void launch_gemm(const float* A, const float* W, const float* bias,
                        float* C, int act,
                        const __nv_bfloat16* bthi, const __nv_bfloat16* btlo)
{
    convert_B<<<KSTACK, 256>>>(W);
    dim3 grid(2, (NN + 127) / 128);
    gemm_hmma<<<grid, 256>>>(A, bthi, btlo, bias, C, NN, act);
}

extern "C" void kernel_launch(void* const* d_in, const int* in_sizes, int n_in,
                              void* d_out, int out_size)
{
    const float* x     = (const float*)d_in[0];
    const int*   ei    = (const int*)  d_in[1];
    const int*   et    = (const int*)  d_in[2];
    const float* w_in  = (const float*)d_in[3];
    const float* b_in  = (const float*)d_in[4];
    const float* c1_w  = (const float*)d_in[5];
    const float* c1_q  = (const float*)d_in[6];
    const float* c1_k  = (const float*)d_in[7];
    const float* c1_b  = (const float*)d_in[8];
    const float* c2_w  = (const float*)d_in[9];
    const float* c2_q  = (const float*)d_in[10];
    const float* c2_k  = (const float*)d_in[11];
    const float* c2_b  = (const float*)d_in[12];
    const float* w_out = (const float*)d_in[13];
    const float* b_out = (const float*)d_in[14];
    const float* w_cls = (const float*)d_in[15];
    const float* b_cls = (const float*)d_in[16];
    float* y = (float*)d_out;

    float *h, *h2, *agg;
    __nv_bfloat16 *bthi, *btlo;
    cudaGetSymbolAddress((void**)&h,    g_h);
    cudaGetSymbolAddress((void**)&h2,   g_h2);
    cudaGetSymbolAddress((void**)&agg,  g_agg);
    cudaGetSymbolAddress((void**)&bthi, g_bthi);
    cudaGetSymbolAddress((void**)&btlo, g_btlo);

    // 1) h = relu(x @ w_in + b_in)
    launch_gemm(x, w_in, b_in, h, 1, bthi, btlo);

    // 2) conv1: h -> h2
    compute_wqk<<<RR, 256>>>(c1_w, c1_q, c1_k);
    node_dots<<<(NN + 7) / 8, 256>>>(h);
    init_md<<<(NN + 255) / 256, 256>>>();
    cudaMemsetAsync(agg, 0, (size_t)NN * KSTACK * sizeof(float));
    edge_pass1<<<(EE + 255) / 256, 256>>>(ei, et);
    edge_pass2<<<(EE + 255) / 256, 256>>>(ei);
    edge_pass3<<<(EE * 32 + 255) / 256, 256>>>(ei, et, h);
    launch_gemm(agg, c1_w, c1_b, h2, 0, bthi, btlo);

    // 3) conv2: h2 -> h
    compute_wqk<<<RR, 256>>>(c2_w, c2_q, c2_k);
    node_dots<<<(NN + 7) / 8, 256>>>(h2);
    init_md<<<(NN + 255) / 256, 256>>>();
    cudaMemsetAsync(agg, 0, (size_t)NN * KSTACK * sizeof(float));
    edge_pass1<<<(EE + 255) / 256, 256>>>(ei, et);
    edge_pass2<<<(EE + 255) / 256, 256>>>(ei);
    edge_pass3<<<(EE * 32 + 255) / 256, 256>>>(ei, et, h2);
    launch_gemm(agg, c2_w, c2_b, h, 0, bthi, btlo);

    // 4) head
    head_kernel<<<NN, 64>>>(h, w_out, b_out, w_cls, b_cls, y);
}

// round 7
// speedup vs baseline: 1.7158x; 1.2546x over previous
#include <cuda_runtime.h>
#include <cuda_bf16.h>
#include <math.h>
#include <cstdint>

#define NN      50000
#define EE      320000
#define RR      3
#define IN_DIM  768
#define HID     256
#define OUT_DIM 64
#define KSTACK  (RR*HID)   // 768

// ---------------- scratch (device globals; no runtime allocation) ----------
__device__ float g_h  [(size_t)NN*HID];
__device__ float g_h2 [(size_t)NN*HID];
__device__ float g_agg[(size_t)NN*KSTACK];
__device__ float g_aq [(size_t)NN*RR];
__device__ float g_ak [(size_t)NN*RR];
__device__ float g_wq [RR*HID];
__device__ float g_wk [RR*HID];
__device__ __nv_bfloat16 g_bthi[(size_t)HID*KSTACK];  // B^T hi [256,768]
__device__ __nv_bfloat16 g_btlo[(size_t)HID*KSTACK];  // B^T lo [256,768]
// CSR scratch
__device__ int g_deg[NN];
__device__ int g_rowstart[NN + 1];
__device__ int g_rowpos[NN];
__device__ int g_bsum[256];
__device__ int g_boff[256];
__device__ int g_csr[EE];          // packed: src | (rt<<20)

#define SCAN_BLOCKS ((NN + 255) / 256)   // 196

// ======================= HMMA GEMM (split-bf16 x3) =========================
#define SROW 40   // bf16 elements per smem row (32 + 8 pad)

__device__ __forceinline__ void mma_bf16(float* c, const uint32_t* a, const uint32_t* b) {
    asm volatile(
        "mma.sync.aligned.m16n8k16.row.col.f32.bf16.bf16.f32 "
        "{%0,%1,%2,%3}, {%4,%5,%6,%7}, {%8,%9}, {%0,%1,%2,%3};"
        : "+f"(c[0]), "+f"(c[1]), "+f"(c[2]), "+f"(c[3])
        : "r"(a[0]), "r"(a[1]), "r"(a[2]), "r"(a[3]), "r"(b[0]), "r"(b[1]));
}

__global__ __launch_bounds__(256, 1) void gemm_hmma(
    const float* __restrict__ A, const __nv_bfloat16* __restrict__ Bthi,
    const __nv_bfloat16* __restrict__ Btlo, const float* __restrict__ bias,
    float* __restrict__ C, int M, int act)
{
    __shared__ __align__(16) __nv_bfloat16 sAhi[128 * SROW];
    __shared__ __align__(16) __nv_bfloat16 sAlo[128 * SROW];
    __shared__ __align__(16) __nv_bfloat16 sBhi[128 * SROW];
    __shared__ __align__(16) __nv_bfloat16 sBlo[128 * SROW];

    const int tid = threadIdx.x, wid = tid >> 5, lane = tid & 31;
    const int g = lane >> 2, t = lane & 3;
    const int m0 = blockIdx.y * 128, n0 = blockIdx.x * 128;
    const int warp_m = wid >> 2, warp_n = wid & 3;   // 2 x 4

    float acc[4][4][4];
#pragma unroll
    for (int i = 0; i < 4; i++)
#pragma unroll
        for (int j = 0; j < 4; j++)
#pragma unroll
            for (int k = 0; k < 4; k++) acc[i][j][k] = 0.f;

    const int srow = tid >> 1, shalf = (tid & 1) * 16;
    const bool arow_ok = (m0 + srow) < M;
    const float* agp = A + (size_t)(m0 + srow) * 768 + shalf;
    const __nv_bfloat16* bhp = Bthi + (size_t)(n0 + srow) * 768 + shalf;
    const __nv_bfloat16* blp = Btlo + (size_t)(n0 + srow) * 768 + shalf;

    float4 a_st[4];
    uint4  bh_st[2], bl_st[2];

    auto load_stage = [&](int kb) {
        if (arow_ok) {
            const float4* ap = (const float4*)(agp + kb);
#pragma unroll
            for (int i = 0; i < 4; i++) a_st[i] = ap[i];
        } else {
#pragma unroll
            for (int i = 0; i < 4; i++) a_st[i] = make_float4(0.f, 0.f, 0.f, 0.f);
        }
        const uint4* bh = (const uint4*)(bhp + kb);
        const uint4* bl = (const uint4*)(blp + kb);
        bh_st[0] = bh[0]; bh_st[1] = bh[1];
        bl_st[0] = bl[0]; bl_st[1] = bl[1];
    };

    auto commit_stage = [&]() {
        uint32_t hi[8], lo[8];
        const float* f = (const float*)a_st;
#pragma unroll
        for (int i = 0; i < 8; i++) {
            float v0 = f[2 * i], v1 = f[2 * i + 1];
            __nv_bfloat16 h0 = __float2bfloat16_rn(v0);
            __nv_bfloat16 h1 = __float2bfloat16_rn(v1);
            __nv_bfloat16 l0 = __float2bfloat16_rn(v0 - __bfloat162float(h0));
            __nv_bfloat16 l1 = __float2bfloat16_rn(v1 - __bfloat162float(h1));
            hi[i] = (uint32_t)__bfloat16_as_ushort(h0) | ((uint32_t)__bfloat16_as_ushort(h1) << 16);
            lo[i] = (uint32_t)__bfloat16_as_ushort(l0) | ((uint32_t)__bfloat16_as_ushort(l1) << 16);
        }
        int off = srow * SROW + shalf;
        *(uint4*)(sAhi + off)     = make_uint4(hi[0], hi[1], hi[2], hi[3]);
        *(uint4*)(sAhi + off + 8) = make_uint4(hi[4], hi[5], hi[6], hi[7]);
        *(uint4*)(sAlo + off)     = make_uint4(lo[0], lo[1], lo[2], lo[3]);
        *(uint4*)(sAlo + off + 8) = make_uint4(lo[4], lo[5], lo[6], lo[7]);
        *(uint4*)(sBhi + off)     = bh_st[0];
        *(uint4*)(sBhi + off + 8) = bh_st[1];
        *(uint4*)(sBlo + off)     = bl_st[0];
        *(uint4*)(sBlo + off + 8) = bl_st[1];
    };

    load_stage(0);

    for (int it = 0; it < 24; it++) {
        __syncthreads();
        commit_stage();
        __syncthreads();
        if (it + 1 < 24) load_stage((it + 1) * 32);

#pragma unroll
        for (int ks = 0; ks < 2; ks++) {
            const int kk = ks * 16 + 2 * t;
            uint32_t ahi[4][4], alo[4][4], bhi[4][2], blo[4][2];
#pragma unroll
            for (int mt = 0; mt < 4; mt++) {
                int r0 = (warp_m * 64 + mt * 16 + g) * SROW;
                int r1 = r0 + 8 * SROW;
                ahi[mt][0] = *(const uint32_t*)(sAhi + r0 + kk);
                ahi[mt][1] = *(const uint32_t*)(sAhi + r1 + kk);
                ahi[mt][2] = *(const uint32_t*)(sAhi + r0 + kk + 8);
                ahi[mt][3] = *(const uint32_t*)(sAhi + r1 + kk + 8);
                alo[mt][0] = *(const uint32_t*)(sAlo + r0 + kk);
                alo[mt][1] = *(const uint32_t*)(sAlo + r1 + kk);
                alo[mt][2] = *(const uint32_t*)(sAlo + r0 + kk + 8);
                alo[mt][3] = *(const uint32_t*)(sAlo + r1 + kk + 8);
            }
#pragma unroll
            for (int nt = 0; nt < 4; nt++) {
                int rb = (warp_n * 32 + nt * 8 + g) * SROW;
                bhi[nt][0] = *(const uint32_t*)(sBhi + rb + kk);
                bhi[nt][1] = *(const uint32_t*)(sBhi + rb + kk + 8);
                blo[nt][0] = *(const uint32_t*)(sBlo + rb + kk);
                blo[nt][1] = *(const uint32_t*)(sBlo + rb + kk + 8);
            }
#pragma unroll
            for (int mt = 0; mt < 4; mt++)
#pragma unroll
                for (int nt = 0; nt < 4; nt++) {
                    mma_bf16(acc[mt][nt], ahi[mt], bhi[nt]);
                    mma_bf16(acc[mt][nt], ahi[mt], blo[nt]);
                    mma_bf16(acc[mt][nt], alo[mt], bhi[nt]);
                }
        }
    }

#pragma unroll
    for (int mt = 0; mt < 4; mt++) {
#pragma unroll
        for (int nt = 0; nt < 4; nt++) {
            int col = n0 + warp_n * 32 + nt * 8 + 2 * t;
            float b0 = __ldg(&bias[col]), b1 = __ldg(&bias[col + 1]);
            int row0 = m0 + warp_m * 64 + mt * 16 + g;
            int row1 = row0 + 8;
            float2 o0 = make_float2(acc[mt][nt][0] + b0, acc[mt][nt][1] + b1);
            float2 o1 = make_float2(acc[mt][nt][2] + b0, acc[mt][nt][3] + b1);
            if (act) {
                o0.x = fmaxf(o0.x, 0.f); o0.y = fmaxf(o0.y, 0.f);
                o1.x = fmaxf(o1.x, 0.f); o1.y = fmaxf(o1.y, 0.f);
            }
            if (row0 < M) *(float2*)&C[(size_t)row0 * 256 + col] = o0;
            if (row1 < M) *(float2*)&C[(size_t)row1 * 256 + col] = o1;
        }
    }
}

__global__ void convert_B(const float* __restrict__ W)
{
    int idx = blockIdx.x * 256 + threadIdx.x;   // 768*256
    int k = idx >> 8, n = idx & 255;
    float v = W[idx];
    __nv_bfloat16 hi = __float2bfloat16_rn(v);
    __nv_bfloat16 lo = __float2bfloat16_rn(v - __bfloat162float(hi));
    g_bthi[(size_t)n * 768 + k] = hi;
    g_btlo[(size_t)n * 768 + k] = lo;
}

// ====================== CSR build (counting sort by dst) ===================
__global__ void zero_i32(int* p, int n)
{
    int i = blockIdx.x * blockDim.x + threadIdx.x;
    if (i < n) p[i] = 0;
}

__global__ void csr_hist(const int* __restrict__ ei)
{
    int e = blockIdx.x * blockDim.x + threadIdx.x;
    if (e >= EE) return;
    int d = ei[EE + e];
    d = (d < 0) ? 0 : (d >= NN ? NN - 1 : d);
    atomicAdd(&g_deg[d], 1);
}

__global__ void csr_scan1()
{
    __shared__ int sc[256];
    int t = threadIdx.x;
    int idx = blockIdx.x * 256 + t;
    int v = (idx < NN) ? g_deg[idx] : 0;
    sc[t] = v;
    __syncthreads();
#pragma unroll
    for (int off = 128; off; off >>= 1) {
        if (t < off) sc[t] += sc[t + off];
        __syncthreads();
    }
    if (t == 0) g_bsum[blockIdx.x] = sc[0];
}

__global__ void csr_scan2()
{
    __shared__ int sc[256];
    int t = threadIdx.x;
    int v = (t < SCAN_BLOCKS) ? g_bsum[t] : 0;
    sc[t] = v;
    __syncthreads();
#pragma unroll
    for (int off = 1; off < 256; off <<= 1) {
        int x = (t >= off) ? sc[t - off] : 0;
        __syncthreads();
        sc[t] += x;
        __syncthreads();
    }
    g_boff[t] = sc[t] - v;   // exclusive
}

__global__ void csr_scan3()
{
    __shared__ int sc[256];
    int t = threadIdx.x;
    int idx = blockIdx.x * 256 + t;
    int v = (idx < NN) ? g_deg[idx] : 0;
    sc[t] = v;
    __syncthreads();
#pragma unroll
    for (int off = 1; off < 256; off <<= 1) {
        int x = (t >= off) ? sc[t - off] : 0;
        __syncthreads();
        sc[t] += x;
        __syncthreads();
    }
    if (idx < NN) {
        int rs = g_boff[blockIdx.x] + sc[t] - v;
        g_rowstart[idx] = rs;
        g_rowpos[idx] = rs;
    }
    if (idx == 0) g_rowstart[NN] = EE;
}

__global__ void csr_scatter(const int* __restrict__ ei, const int* __restrict__ et)
{
    int e = blockIdx.x * blockDim.x + threadIdx.x;
    if (e >= EE) return;
    int s = ei[e], d = ei[EE + e], r = et[e];
    s = (s < 0) ? 0 : (s >= NN ? NN - 1 : s);
    d = (d < 0) ? 0 : (d >= NN ? NN - 1 : d);
    r = (r < 0) ? 0 : (r >= RR ? RR - 1 : r);
    int pos = atomicAdd(&g_rowpos[d], 1);
    if (pos >= 0 && pos < EE) g_csr[pos] = s | (r << 20);
}

// ====================== attention precompute ===============================
__global__ void compute_wqk(const float* __restrict__ W, const float* __restrict__ q,
                            const float* __restrict__ k)
{
    int r = blockIdx.x, i = threadIdx.x;
    const float* wr = &W[(size_t)r * HID * HID + (size_t)i * HID];
    float sq = 0.f, sk = 0.f;
#pragma unroll 8
    for (int j = 0; j < HID; j++) {
        float w = wr[j];
        sq = fmaf(w, q[j], sq);
        sk = fmaf(w, k[j], sk);
    }
    g_wq[r * HID + i] = sq;
    g_wk[r * HID + i] = sk;
}

__global__ void node_dots(const float* __restrict__ h)
{
    int warp = (blockIdx.x * blockDim.x + threadIdx.x) >> 5;
    int lane = threadIdx.x & 31;
    if (warp >= NN) return;
    float sq[RR] = {0.f, 0.f, 0.f}, sk[RR] = {0.f, 0.f, 0.f};
#pragma unroll
    for (int i = 0; i < 8; i++) {
        int idx = i * 32 + lane;
        float hv = h[(size_t)warp * HID + idx];
#pragma unroll
        for (int r = 0; r < RR; r++) {
            sq[r] = fmaf(hv, g_wq[r * HID + idx], sq[r]);
            sk[r] = fmaf(hv, g_wk[r * HID + idx], sk[r]);
        }
    }
#pragma unroll
    for (int off = 16; off; off >>= 1) {
#pragma unroll
        for (int r = 0; r < RR; r++) {
            sq[r] += __shfl_xor_sync(0xFFFFFFFFu, sq[r], off);
            sk[r] += __shfl_xor_sync(0xFFFFFFFFu, sk[r], off);
        }
    }
    if (lane == 0) {
#pragma unroll
        for (int r = 0; r < RR; r++) {
            g_aq[(size_t)warp * RR + r] = sq[r];
            g_ak[(size_t)warp * RR + r] = sk[r];
        }
    }
}

// ============ fused softmax + aggregation: one warp per dst node ===========
// agg[n, r*256+c] = sum_{e in CSR[n], type r} softmax_coef(e) * h[src_e, c]
__global__ __launch_bounds__(256) void agg_fused(
    const float* __restrict__ h, float* __restrict__ agg)
{
    int warp = (int)((blockIdx.x * blockDim.x + threadIdx.x) >> 5);
    int lane = threadIdx.x & 31;
    if (warp >= NN) return;
    int e0 = g_rowstart[warp], e1 = g_rowstart[warp + 1];
    e0 = (e0 < 0) ? 0 : (e0 > EE ? EE : e0);
    e1 = (e1 < e0) ? e0 : (e1 > EE ? EE : e1);

    float aq0 = g_aq[warp * 3 + 0], aq1 = g_aq[warp * 3 + 1], aq2 = g_aq[warp * 3 + 2];

    // phase A: segment max (lane-parallel)
    float m = -INFINITY;
    for (int i = e0 + lane; i < e1; i += 32) {
        int p = g_csr[i];
        int s = p & 0xFFFFF, r = (p >> 20) & 3;
        if (s >= NN) s = NN - 1;
        if (r >= RR) r = RR - 1;
        float a = (r == 0 ? aq0 : (r == 1 ? aq1 : aq2)) + __ldg(&g_ak[s * 3 + r]);
        a = a > 0.f ? a : 0.2f * a;
        m = fmaxf(m, a);
    }
#pragma unroll
    for (int off = 16; off; off >>= 1) m = fmaxf(m, __shfl_xor_sync(0xFFFFFFFFu, m, off));

    // phase B: sum of exp
    float dsum = 0.f;
    for (int i = e0 + lane; i < e1; i += 32) {
        int p = g_csr[i];
        int s = p & 0xFFFFF, r = (p >> 20) & 3;
        if (s >= NN) s = NN - 1;
        if (r >= RR) r = RR - 1;
        float a = (r == 0 ? aq0 : (r == 1 ? aq1 : aq2)) + __ldg(&g_ak[s * 3 + r]);
        a = a > 0.f ? a : 0.2f * a;
        dsum += __expf(a - m);
    }
#pragma unroll
    for (int off = 16; off; off >>= 1) dsum += __shfl_xor_sync(0xFFFFFFFFu, dsum, off);
    float inv = 1.f / (dsum + 1e-16f);

    // phase C: whole warp per edge; each lane owns 8 channels
    float4 a0l = make_float4(0.f, 0.f, 0.f, 0.f), a0h = a0l;
    float4 a1l = a0l, a1h = a0l, a2l = a0l, a2h = a0l;
    for (int j = e0; j < e1; j++) {
        int p = g_csr[j];                 // uniform across warp (broadcast)
        int s = p & 0xFFFFF, r = (p >> 20) & 3;
        if (s >= NN) s = NN - 1;
        if (r >= RR) r = RR - 1;
        float a = (r == 0 ? aq0 : (r == 1 ? aq1 : aq2)) + g_ak[s * 3 + r];
        a = a > 0.f ? a : 0.2f * a;
        float c = __expf(a - m) * inv;
        const float4* hp = (const float4*)(h + (size_t)s * HID);
        float4 v0 = hp[lane];
        float4 v1 = hp[32 + lane];
        if (r == 0) {
            a0l.x = fmaf(c, v0.x, a0l.x); a0l.y = fmaf(c, v0.y, a0l.y);
            a0l.z = fmaf(c, v0.z, a0l.z); a0l.w = fmaf(c, v0.w, a0l.w);
            a0h.x = fmaf(c, v1.x, a0h.x); a0h.y = fmaf(c, v1.y, a0h.y);
            a0h.z = fmaf(c, v1.z, a0h.z); a0h.w = fmaf(c, v1.w, a0h.w);
        } else if (r == 1) {
            a1l.x = fmaf(c, v0.x, a1l.x); a1l.y = fmaf(c, v0.y, a1l.y);
            a1l.z = fmaf(c, v0.z, a1l.z); a1l.w = fmaf(c, v0.w, a1l.w);
            a1h.x = fmaf(c, v1.x, a1h.x); a1h.y = fmaf(c, v1.y, a1h.y);
            a1h.z = fmaf(c, v1.z, a1h.z); a1h.w = fmaf(c, v1.w, a1h.w);
        } else {
            a2l.x = fmaf(c, v0.x, a2l.x); a2l.y = fmaf(c, v0.y, a2l.y);
            a2l.z = fmaf(c, v0.z, a2l.z); a2l.w = fmaf(c, v0.w, a2l.w);
            a2h.x = fmaf(c, v1.x, a2h.x); a2h.y = fmaf(c, v1.y, a2h.y);
            a2h.z = fmaf(c, v1.z, a2h.z); a2h.w = fmaf(c, v1.w, a2h.w);
        }
    }
    float* ag = agg + (size_t)warp * KSTACK;
    *(float4*)(ag + 0 * HID + lane * 4)       = a0l;
    *(float4*)(ag + 0 * HID + 128 + lane * 4) = a0h;
    *(float4*)(ag + 1 * HID + lane * 4)       = a1l;
    *(float4*)(ag + 1 * HID + 128 + lane * 4) = a1h;
    *(float4*)(ag + 2 * HID + lane * 4)       = a2l;
    *(float4*)(ag + 2 * HID + 128 + lane * 4) = a2h;
}

// ====================== head ===============================================
__global__ __launch_bounds__(64) void head_kernel(
    const float* __restrict__ h, const float* __restrict__ w_out,
    const float* __restrict__ b_out, const float* __restrict__ w_cls,
    const float* __restrict__ b_cls, float* __restrict__ y)
{
    int n = blockIdx.x;
    int o = threadIdx.x;
    __shared__ float hs[HID];
    __shared__ float ts[OUT_DIM];
#pragma unroll
    for (int i = o; i < HID; i += 64) hs[i] = h[(size_t)n * HID + i];
    __syncthreads();
    float s = b_out[o];
#pragma unroll 8
    for (int c = 0; c < HID; c++)
        s = fmaf(hs[c], w_out[c * OUT_DIM + o], s);
    ts[o] = fmaxf(s, 0.f);
    __syncthreads();
    if (o < 2) {
        float acc = b_cls[o];
#pragma unroll
        for (int j = 0; j < OUT_DIM; j++)
            acc = fmaf(ts[j], w_cls[j * 2 + o], acc);
        y[(size_t)n * 2 + o] = acc;
    }
}

// ---------------------------------------------------------------------------
static void launch_gemm(const float* A, const float* W, const float* bias,
                        float* C, int act,
                        const __nv_bfloat16* bthi, const __nv_bfloat16* btlo)
{
    convert_B<<<KSTACK, 256>>>(W);
    dim3 grid(2, (NN + 127) / 128);
    gemm_hmma<<<grid, 256>>>(A, bthi, btlo, bias, C, NN, act);
}

extern "C" void kernel_launch(void* const* d_in, const int* in_sizes, int n_in,
                              void* d_out, int out_size)
{
    const float* x     = (const float*)d_in[0];
    const int*   ei    = (const int*)  d_in[1];
    const int*   et    = (const int*)  d_in[2];
    const float* w_in  = (const float*)d_in[3];
    const float* b_in  = (const float*)d_in[4];
    const float* c1_w  = (const float*)d_in[5];
    const float* c1_q  = (const float*)d_in[6];
    const float* c1_k  = (const float*)d_in[7];
    const float* c1_b  = (const float*)d_in[8];
    const float* c2_w  = (const float*)d_in[9];
    const float* c2_q  = (const float*)d_in[10];
    const float* c2_k  = (const float*)d_in[11];
    const float* c2_b  = (const float*)d_in[12];
    const float* w_out = (const float*)d_in[13];
    const float* b_out = (const float*)d_in[14];
    const float* w_cls = (const float*)d_in[15];
    const float* b_cls = (const float*)d_in[16];
    float* y = (float*)d_out;

    float *h, *h2, *agg;
    __nv_bfloat16 *bthi, *btlo;
    int* deg;
    cudaGetSymbolAddress((void**)&h,    g_h);
    cudaGetSymbolAddress((void**)&h2,   g_h2);
    cudaGetSymbolAddress((void**)&agg,  g_agg);
    cudaGetSymbolAddress((void**)&bthi, g_bthi);
    cudaGetSymbolAddress((void**)&btlo, g_btlo);
    cudaGetSymbolAddress((void**)&deg,  g_deg);

    // ---- CSR build (once; shared by both convs) ----
    zero_i32<<<(NN + 255) / 256, 256>>>(deg, NN);
    csr_hist<<<(EE + 255) / 256, 256>>>(ei);
    csr_scan1<<<SCAN_BLOCKS, 256>>>();
    csr_scan2<<<1, 256>>>();
    csr_scan3<<<SCAN_BLOCKS, 256>>>();
    csr_scatter<<<(EE + 255) / 256, 256>>>(ei, et);

    // 1) h = relu(x @ w_in + b_in)
    launch_gemm(x, w_in, b_in, h, 1, bthi, btlo);

    // 2) conv1: h -> h2
    compute_wqk<<<RR, 256>>>(c1_w, c1_q, c1_k);
    node_dots<<<(NN + 7) / 8, 256>>>(h);
    agg_fused<<<(NN * 32 + 255) / 256, 256>>>(h, agg);
    launch_gemm(agg, c1_w, c1_b, h2, 0, bthi, btlo);

    // 3) conv2: h2 -> h
    compute_wqk<<<RR, 256>>>(c2_w, c2_q, c2_k);
    node_dots<<<(NN + 7) / 8, 256>>>(h2);
    agg_fused<<<(NN * 32 + 255) / 256, 256>>>(h2, agg);
    launch_gemm(agg, c2_w, c2_b, h, 0, bthi, btlo);

    // 4) head
    head_kernel<<<NN, 64>>>(h, w_out, b_out, w_cls, b_cls, y);
}